// round 9
// baseline (speedup 1.0000x reference)
#include <cuda_runtime.h>
#include <stdint.h>

#define H 2048
#define W 2048
#define KS 11
#define PS 10
#define PAD 5
#define HO 205                 // conv output: floor((2048+10-11)/10)+1
#define OUT 2255               // 205 * (PS+1)
#define CELLS (HO*HO)
#define ROWS_TOTAL (3*OUT)
#define CELL_BLOCKS ((CELLS + 7) / 8)   // 5254

// Intermediate per-cell result: [3][HO][HO] (+pad for safe over-read)
__device__ float g_mid[3 * HO * HO + 8];
// Per-oh completion counters (reset to 0 by memset node each launch)
__device__ int g_cnt[HO];

// ---------------------------------------------------------------------------
// Fused kernel.
// Blocks [0, CELL_BLOCKS): one warp per cell (R5/R7 measured-fastest body).
//   After writing its 3 g_mid values, lane 0 fences + bumps g_cnt[oh].
// Blocks [CELL_BLOCKS, +ROWS_TOTAL): one block per output row. Live rows
//   acquire-spin until g_cnt[oh]==205, pad rows write zeros immediately.
// Deadlock-free: cell blocks have lower IDs -> dispatched first, never wait.
// ---------------------------------------------------------------------------
__global__ void __launch_bounds__(256) fused_kernel(const float* __restrict__ rgb,
                                                    float* __restrict__ out) {
    if (blockIdx.x < CELL_BLOCKS) {
        // ================= CELL PART =================
        const int wid = (blockIdx.x * blockDim.x + threadIdx.x) >> 5;
        if (wid >= CELLS) return;
        const int lane = threadIdx.x & 31;

        const int oh = wid / HO;
        const int ow = wid - oh * HO;
        const int y0 = oh * PS - PAD;
        const int x0 = ow * PS - PAD;

        const float* __restrict__ rp = rgb;
        const float* __restrict__ gp = rgb + H * W;
        const float* __restrict__ bp = rgb + 2 * H * W;

        // p = lane + 32t; 121 px: t=0..2 always active, t=3 iff lane<25.
        int off[4];
        bool act[4];
        act[0] = true; act[1] = true; act[2] = true; act[3] = (lane < 25);
#pragma unroll
        for (int t = 0; t < 4; t++) {
            const int p = lane + t * 32;
            const int dy = p / KS;
            const int dx = p - dy * KS;
            off[t] = (y0 + dy) * W + (x0 + dx);
        }
        if ((oh == 0) | (ow == 0)) {   // border cells: 409 of 42025
#pragma unroll
            for (int t = 0; t < 4; t++) {
                const int p = lane + t * 32;
                const int dy = p / KS;
                const int dx = p - dy * KS;
                act[t] = act[t] && (y0 + dy >= 0) && (x0 + dx >= 0);
            }
        }

        // Batch ALL loads before any consumer (max MLP — measured critical).
        float rv[4], gv[4], bv[4];
#pragma unroll
        for (int t = 0; t < 4; t++) rv[t] = act[t] ? __ldg(rp + off[t]) : 0.0f;
#pragma unroll
        for (int t = 0; t < 4; t++) gv[t] = act[t] ? __ldg(gp + off[t]) : 0.0f;
#pragma unroll
        for (int t = 0; t < 4; t++) bv[t] = act[t] ? __ldg(bp + off[t]) : 0.0f;

        // Bin + packed histogram (8-bit counters; totals <=121: carry-free)
        int bn[4];
        unsigned long long hlo = 0ULL, hhi = 0ULL;
#pragma unroll
        for (int t = 0; t < 4; t++) {
            const float s = __fadd_rn(__fadd_rn(rv[t], gv[t]), bv[t]);
            const int bi = (int)(__fmul_rn(s, 0.020833334f));   // 1/48 rn
            bn[t] = bi;
            if (act[t]) {
                const unsigned long long inc = 1ULL << ((bi & 7) * 8);
                if (bi < 8) hlo += inc; else hhi += inc;
            }
        }

        const unsigned h0 = __reduce_add_sync(0xffffffffu, (unsigned)hlo);
        const unsigned h1 = __reduce_add_sync(0xffffffffu, (unsigned)(hlo >> 32));
        const unsigned h2 = __reduce_add_sync(0xffffffffu, (unsigned)hhi);
        const unsigned h3 = __reduce_add_sync(0xffffffffu, (unsigned)(hhi >> 32));

        // Lane-parallel argmax; ties -> smaller bin (jnp.argmax first-max).
        const int b = lane & 15;
        const unsigned hw = (b < 8) ? ((b < 4) ? h0 : h1) : ((b < 12) ? h2 : h3);
        const unsigned cnt = (hw >> ((b & 3) * 8)) & 0xFFu;
        const unsigned key = (cnt << 4) | (unsigned)(15 - b);
        const unsigned kmax = __reduce_max_sync(0xffffffffu, key);
        const int amax = 15 - (int)(kmax & 15u);
        const float cm = (float)(kmax >> 4);

        float sr = 0.f, sg = 0.f, sb = 0.f;
#pragma unroll
        for (int t = 0; t < 4; t++) {
            if (bn[t] == amax) { sr += rv[t]; sg += gv[t]; sb += bv[t]; }
        }
#pragma unroll
        for (int s = 16; s > 0; s >>= 1) {
            sr += __shfl_xor_sync(0xffffffffu, sr, s);
            sg += __shfl_xor_sync(0xffffffffu, sg, s);
            sb += __shfl_xor_sync(0xffffffffu, sb, s);
        }

        if (lane == 0) {
            const float inv = __frcp_rn(cm);
            g_mid[wid]               = __fmul_rn(sr, inv);
            g_mid[wid + HO * HO]     = __fmul_rn(sg, inv);
            g_mid[wid + 2 * HO * HO] = __fmul_rn(sb, inv);
            __threadfence();                       // publish before count
            atomicAdd(&g_cnt[oh], 1);
        }
        return;
    }

    // ================= UPSAMPLE PART =================
    const int row = blockIdx.x - CELL_BLOCKS;      // 0 .. 3*2255-1
    const int tid = threadIdx.x;
    const unsigned ur = (unsigned)row;
    const unsigned c = ur / (unsigned)OUT;
    const unsigned y = ur - c * (unsigned)OUT;
    const unsigned oh = y / 11u;
    const unsigned ii = y - oh * 11u;

    float* __restrict__ orow = out + (size_t)row * OUT;
    const int h = (int)((4u - ((ur * (unsigned)OUT) & 3u)) & 3u);
    const int nv = (OUT - h) >> 2;
    const int nt = OUT - h - nv * 4;
    float4* __restrict__ ov = (float4*)(orow + h);

    if (ii == 10u) {                   // pad row: zeros, no dependency
        if (tid < h) orow[tid] = 0.0f;
        if (tid >= 4 && tid < 4 + nt) orow[h + nv * 4 + (tid - 4)] = 0.0f;
        const float4 z = make_float4(0.f, 0.f, 0.f, 0.f);
        for (int v = tid; v < nv; v += 256) ov[v] = z;
        return;
    }

    // Wait until mid row oh is complete (205 cells).
    if (tid == 0) {
        const int* cp = &g_cnt[oh];
        int v;
        do {
            asm volatile("ld.acquire.gpu.global.b32 %0, [%1];"
                         : "=r"(v) : "l"(cp) : "memory");
            if (v >= HO) break;
            __nanosleep(128);
        } while (true);
    }
    __syncthreads();

    const float* __restrict__ midc = g_mid + c * HO * HO + oh * HO;

    // Scalar head (x <= 2: o=0, j<10 -> always live)
    if (tid < h) orow[tid] = __ldg(midc);
    // Scalar tail (x in 2252..2254)
    if (tid >= 4 && tid < 4 + nt) {
        const unsigned x = (unsigned)(h + nv * 4 + (tid - 4));
        const unsigned o = x / 11u;
        const unsigned j = x - o * 11u;
        orow[x] = (j < 10u) ? __ldg(midc + o) : 0.0f;
    }

    // Vector body: 4 independent magic-divs per float4, no divergence
    for (int v = tid; v < nv; v += 256) {
        const unsigned x0 = (unsigned)(h + v * 4);
        float4 o;
        float* po = &o.x;
#pragma unroll
        for (int k = 0; k < 4; k++) {
            const unsigned x = x0 + (unsigned)k;
            const unsigned ow2 = x / 11u;
            const unsigned j = x - ow2 * 11u;
            po[k] = (j < 10u) ? __ldg(midc + ow2) : 0.0f;
        }
        ov[v] = o;
    }
}

extern "C" void kernel_launch(void* const* d_in, const int* in_sizes, int n_in,
                              void* d_out, int out_size) {
    const float* rgb = (const float*)d_in[0];
    float* out = (float*)d_out;

    // Zero the per-row counters (graph-capturable memset node, runs each replay)
    void* cnt_ptr = nullptr;
    cudaGetSymbolAddress(&cnt_ptr, g_cnt);
    cudaMemsetAsync(cnt_ptr, 0, HO * sizeof(int), 0);

    fused_kernel<<<CELL_BLOCKS + ROWS_TOTAL, 256>>>(rgb, out);
}

// round 10
// speedup vs baseline: 1.1806x; 1.1806x over previous
#include <cuda_runtime.h>
#include <stdint.h>

#define H 2048
#define W 2048
#define KS 11
#define PS 10
#define PAD 5
#define HO 205                 // conv output: floor((2048+10-11)/10)+1
#define OUT 2255               // 205 * (PS+1)
#define CELLS (HO*HO)
#define ROWS_TOTAL (3*OUT)

// Intermediate per-cell result: [3][HO][HO] (+pad for safe over-read)
__device__ float g_mid[3 * HO * HO + 8];

// ---------------------------------------------------------------------------
// Kernel 1: one warp per output cell, direct LDG, batched loads (MLP=12).
// Interior warps (99%) load unconditionally (no select ALU); border warps
// take the predicated path. Histogram in packed 8-bit counters + redux;
// argmax via one reduce-max (first-max tie-break like jnp.argmax);
// masked channel sums in 16.16 fixed point via 3x redux (no shfl chain).
// ---------------------------------------------------------------------------
__global__ void __launch_bounds__(256) cell_kernel(const float* __restrict__ rgb) {
    const int wid = (blockIdx.x * blockDim.x + threadIdx.x) >> 5;
    if (wid >= CELLS) return;
    const int lane = threadIdx.x & 31;

    const int oh = wid / HO;
    const int ow = wid - oh * HO;
    const int y0 = oh * PS - PAD;
    const int x0 = ow * PS - PAD;
    const bool border = (oh == 0) | (ow == 0);   // 409 of 42025, warp-uniform

    const float* __restrict__ rp = rgb;
    const float* __restrict__ gp = rgb + H * W;
    const float* __restrict__ bp = rgb + 2 * H * W;

    // p = lane + 32t, clamped to 120 for t=3 lanes>=25 (dup load, masked later)
    int off[4];
    bool act[4];
    act[0] = true; act[1] = true; act[2] = true; act[3] = (lane < 25);
#pragma unroll
    for (int t = 0; t < 4; t++) {
        int p = lane + t * 32;
        if (t == 3) p = p > 120 ? 120 : p;
        const int dy = p / KS;
        const int dx = p - dy * KS;
        off[t] = (y0 + dy) * W + (x0 + dx);
        if (border)
            act[t] = act[t] && (y0 + dy >= 0) && (x0 + dx >= 0);
    }

    // Batch ALL loads before any consumer (MLP=12 — measured critical).
    float rv[4], gv[4], bv[4];
    if (!border) {
#pragma unroll
        for (int t = 0; t < 4; t++) rv[t] = __ldg(rp + off[t]);
#pragma unroll
        for (int t = 0; t < 4; t++) gv[t] = __ldg(gp + off[t]);
#pragma unroll
        for (int t = 0; t < 4; t++) bv[t] = __ldg(bp + off[t]);
    } else {
#pragma unroll
        for (int t = 0; t < 4; t++) rv[t] = act[t] ? __ldg(rp + off[t]) : 0.0f;
#pragma unroll
        for (int t = 0; t < 4; t++) gv[t] = act[t] ? __ldg(gp + off[t]) : 0.0f;
#pragma unroll
        for (int t = 0; t < 4; t++) bv[t] = act[t] ? __ldg(bp + off[t]) : 0.0f;
    }

    // Bin + packed histogram (8-bit counters; totals <=121: carry-free).
    // bn = 16 sentinel for dead slots (never equals amax <= 15).
    int bn[4];
    unsigned long long hlo = 0ULL, hhi = 0ULL;
#pragma unroll
    for (int t = 0; t < 4; t++) {
        const float s = __fadd_rn(__fadd_rn(rv[t], gv[t]), bv[t]);
        const int bi = (int)(__fmul_rn(s, 0.020833334f));   // 1/48 rn
        bn[t] = act[t] ? bi : 16;
        if (act[t]) {
            const unsigned long long inc = 1ULL << ((bi & 7) * 8);
            if (bi < 8) hlo += inc; else hhi += inc;
        }
    }

    const unsigned h0 = __reduce_add_sync(0xffffffffu, (unsigned)hlo);
    const unsigned h1 = __reduce_add_sync(0xffffffffu, (unsigned)(hlo >> 32));
    const unsigned h2 = __reduce_add_sync(0xffffffffu, (unsigned)hhi);
    const unsigned h3 = __reduce_add_sync(0xffffffffu, (unsigned)(hhi >> 32));

    // Lane-parallel argmax; ties -> smaller bin (jnp.argmax first-max).
    const int b = lane & 15;
    const unsigned hw = (b < 8) ? ((b < 4) ? h0 : h1) : ((b < 12) ? h2 : h3);
    const unsigned cnt = (hw >> ((b & 3) * 8)) & 0xFFu;
    const unsigned key = (cnt << 4) | (unsigned)(15 - b);
    const unsigned kmax = __reduce_max_sync(0xffffffffu, key);
    const int amax = 15 - (int)(kmax & 15u);
    const float cm = (float)(kmax >> 4);

    // Masked channel sums in 16.16 fixed point: pixel < 256 so
    // sum < 121*255*2^16 = 2.02e9 < 2^31. Error <= 121*2^-16 abs (negligible).
    int sri = 0, sgi = 0, sbi = 0;
#pragma unroll
    for (int t = 0; t < 4; t++) {
        if (bn[t] == amax) {
            sri += (int)(rv[t] * 65536.0f);
            sgi += (int)(gv[t] * 65536.0f);
            sbi += (int)(bv[t] * 65536.0f);
        }
    }
    const unsigned sru = __reduce_add_sync(0xffffffffu, (unsigned)sri);
    const unsigned sgu = __reduce_add_sync(0xffffffffu, (unsigned)sgi);
    const unsigned sbu = __reduce_add_sync(0xffffffffu, (unsigned)sbi);

    if (lane == 0) {
        const float inv = __fmul_rn(__frcp_rn(cm), 1.52587890625e-05f); // /2^16
        g_mid[wid]               = __fmul_rn((float)sru, inv);
        g_mid[wid + HO * HO]     = __fmul_rn((float)sgu, inv);
        g_mid[wid + 2 * HO * HO] = __fmul_rn((float)sbu, inv);
    }
}

// ---------------------------------------------------------------------------
// Kernel 2: upsample 205x205 -> 2255x2255 per channel.
// One 128-thread block per output row (measured-best shape); body emits
// 8 floats (2 aligned STG.128) per iteration from ONE magic-div + 2 LDGs
// (an 8-px span crosses at most one 11-block boundary: j0<=10 -> j0+7<=17).
// ---------------------------------------------------------------------------
__global__ void __launch_bounds__(128) upsample_kernel(float* __restrict__ out) {
    const int row = blockIdx.x;            // 0 .. 3*2255-1
    const int tid = threadIdx.x;
    const unsigned ur = (unsigned)row;
    const unsigned c = ur / (unsigned)OUT;
    const unsigned y = ur - c * (unsigned)OUT;
    const unsigned oh = y / 11u;
    const unsigned ii = y - oh * 11u;

    float* __restrict__ orow = out + (size_t)row * OUT;
    const int h = (int)((4u - ((ur * (unsigned)OUT) & 3u)) & 3u);

    if (ii == 10u) {                       // pad row: zeros
        const int nv = (OUT - h) >> 2;
        const int nt = OUT - h - nv * 4;
        float4* __restrict__ ov = (float4*)(orow + h);
        if (tid < h) orow[tid] = 0.0f;
        if (tid >= 4 && tid < 4 + nt) orow[h + nv * 4 + (tid - 4)] = 0.0f;
        const float4 z = make_float4(0.f, 0.f, 0.f, 0.f);
        for (int v = tid; v < nv; v += 128) ov[v] = z;
        return;
    }

    const float* __restrict__ midc = g_mid + c * HO * HO + oh * HO;

    const int n8 = (OUT - h) >> 3;         // 8-float groups (281)
    const int tail_start = h + n8 * 8;
    const int ntail = OUT - tail_start;    // 0..7

    // Scalar head (x <= 2: ow=0, j<10 -> always live)
    if (tid < h) orow[tid] = __ldg(midc);
    // Scalar tail (up to 7 elements), threads 4..10
    if (tid >= 4 && tid < 4 + ntail) {
        const unsigned x = (unsigned)(tail_start + (tid - 4));
        const unsigned o = x / 11u;
        const unsigned j = x - o * 11u;
        orow[x] = (j < 10u) ? __ldg(midc + o) : 0.0f;
    }

    // Body: 8 outputs per iteration, one division, two LDG, two STG.128.
    for (int g = tid; g < n8; g += 128) {
        const unsigned x0 = (unsigned)(h + g * 8);
        const unsigned ow0 = x0 / 11u;
        const int j0 = (int)(x0 - ow0 * 11u);          // 0..10
        const float m0 = __ldg(midc + ow0);
        const float m1 = __ldg(midc + ow0 + 1);        // padded global; safe
        float e[8];
#pragma unroll
        for (int k = 0; k < 8; k++) {
            const int j = j0 + k;                      // <= 17
            e[k] = (j < 10) ? m0 : ((j == 10) ? 0.0f : m1);
        }
        float4* __restrict__ p = (float4*)(orow + x0);
        p[0] = make_float4(e[0], e[1], e[2], e[3]);
        p[1] = make_float4(e[4], e[5], e[6], e[7]);
    }
}

extern "C" void kernel_launch(void* const* d_in, const int* in_sizes, int n_in,
                              void* d_out, int out_size) {
    const float* rgb = (const float*)d_in[0];
    float* out = (float*)d_out;

    const int blocks1 = (CELLS + 7) / 8;       // one warp per cell, 8/block
    cell_kernel<<<blocks1, 256>>>(rgb);

    upsample_kernel<<<ROWS_TOTAL, 128>>>(out); // one block per output row
}

// round 11
// speedup vs baseline: 1.3125x; 1.1117x over previous
#include <cuda_runtime.h>
#include <stdint.h>

#define H 2048
#define W 2048
#define KS 11
#define PS 10
#define PAD 5
#define HO 205                 // conv output: floor((2048+10-11)/10)+1
#define OUT 2255               // 205 * (PS+1)
#define CELLS (HO*HO)
#define BANDS (3*HO)           // (channel, oh) output bands of 11 rows

// Intermediate per-cell result: [3][HO][HO] (+pad for safe over-read)
__device__ float g_mid[3 * HO * HO + 8];

__device__ __forceinline__ unsigned smem_u32(const void* p) {
    unsigned a;
    asm("{ .reg .u64 t; cvta.to.shared.u64 t, %1; cvt.u32.u64 %0, t; }"
        : "=r"(a) : "l"(p));
    return a;
}

// ---------------------------------------------------------------------------
// Kernel 1: one warp per output cell (R10 body — best measured class).
// ---------------------------------------------------------------------------
__global__ void __launch_bounds__(256) cell_kernel(const float* __restrict__ rgb) {
    const int wid = (blockIdx.x * blockDim.x + threadIdx.x) >> 5;
    if (wid >= CELLS) return;
    const int lane = threadIdx.x & 31;

    const int oh = wid / HO;
    const int ow = wid - oh * HO;
    const int y0 = oh * PS - PAD;
    const int x0 = ow * PS - PAD;
    const bool border = (oh == 0) | (ow == 0);   // 409 of 42025, warp-uniform

    const float* __restrict__ rp = rgb;
    const float* __restrict__ gp = rgb + H * W;
    const float* __restrict__ bp = rgb + 2 * H * W;

    int off[4];
    bool act[4];
    act[0] = true; act[1] = true; act[2] = true; act[3] = (lane < 25);
#pragma unroll
    for (int t = 0; t < 4; t++) {
        int p = lane + t * 32;
        if (t == 3) p = p > 120 ? 120 : p;       // dup load, masked later
        const int dy = p / KS;
        const int dx = p - dy * KS;
        off[t] = (y0 + dy) * W + (x0 + dx);
        if (border)
            act[t] = act[t] && (y0 + dy >= 0) && (x0 + dx >= 0);
    }

    // Batch ALL loads before any consumer (MLP=12 — measured critical).
    float rv[4], gv[4], bv[4];
    if (!border) {
#pragma unroll
        for (int t = 0; t < 4; t++) rv[t] = __ldg(rp + off[t]);
#pragma unroll
        for (int t = 0; t < 4; t++) gv[t] = __ldg(gp + off[t]);
#pragma unroll
        for (int t = 0; t < 4; t++) bv[t] = __ldg(bp + off[t]);
    } else {
#pragma unroll
        for (int t = 0; t < 4; t++) rv[t] = act[t] ? __ldg(rp + off[t]) : 0.0f;
#pragma unroll
        for (int t = 0; t < 4; t++) gv[t] = act[t] ? __ldg(gp + off[t]) : 0.0f;
#pragma unroll
        for (int t = 0; t < 4; t++) bv[t] = act[t] ? __ldg(bp + off[t]) : 0.0f;
    }

    // Bin + packed histogram (8-bit counters; totals <=121: carry-free).
    int bn[4];
    unsigned long long hlo = 0ULL, hhi = 0ULL;
#pragma unroll
    for (int t = 0; t < 4; t++) {
        const float s = __fadd_rn(__fadd_rn(rv[t], gv[t]), bv[t]);
        const int bi = (int)(__fmul_rn(s, 0.020833334f));   // 1/48 rn
        bn[t] = act[t] ? bi : 16;                            // 16 = dead
        if (act[t]) {
            const unsigned long long inc = 1ULL << ((bi & 7) * 8);
            if (bi < 8) hlo += inc; else hhi += inc;
        }
    }

    const unsigned h0 = __reduce_add_sync(0xffffffffu, (unsigned)hlo);
    const unsigned h1 = __reduce_add_sync(0xffffffffu, (unsigned)(hlo >> 32));
    const unsigned h2 = __reduce_add_sync(0xffffffffu, (unsigned)hhi);
    const unsigned h3 = __reduce_add_sync(0xffffffffu, (unsigned)(hhi >> 32));

    // Lane-parallel argmax; ties -> smaller bin (jnp.argmax first-max).
    const int b = lane & 15;
    const unsigned hw = (b < 8) ? ((b < 4) ? h0 : h1) : ((b < 12) ? h2 : h3);
    const unsigned cnt = (hw >> ((b & 3) * 8)) & 0xFFu;
    const unsigned key = (cnt << 4) | (unsigned)(15 - b);
    const unsigned kmax = __reduce_max_sync(0xffffffffu, key);
    const int amax = 15 - (int)(kmax & 15u);
    const float cm = (float)(kmax >> 4);

    // Masked channel sums in 16.16 fixed point (sum < 2^31; err ~1e-7 rel).
    int sri = 0, sgi = 0, sbi = 0;
#pragma unroll
    for (int t = 0; t < 4; t++) {
        if (bn[t] == amax) {
            sri += (int)(rv[t] * 65536.0f);
            sgi += (int)(gv[t] * 65536.0f);
            sbi += (int)(bv[t] * 65536.0f);
        }
    }
    const unsigned sru = __reduce_add_sync(0xffffffffu, (unsigned)sri);
    const unsigned sgu = __reduce_add_sync(0xffffffffu, (unsigned)sgi);
    const unsigned sbu = __reduce_add_sync(0xffffffffu, (unsigned)sbi);

    if (lane == 0) {
        const float inv = __fmul_rn(__frcp_rn(cm), 1.52587890625e-05f);
        g_mid[wid]               = __fmul_rn((float)sru, inv);
        g_mid[wid + HO * HO]     = __fmul_rn((float)sgu, inv);
        g_mid[wid + 2 * HO * HO] = __fmul_rn((float)sbu, inv);
    }
}

// ---------------------------------------------------------------------------
// Kernel 2: upsample via TMA bulk stores. One block per band (c, oh).
// Build the 2255-float expanded row template in smem in 4 shift phases
// (sbuf[a][k] = T[a+k], so every 16B-aligned gmem body has an aligned,
// 16B-multiple smem source) + one zero buffer for the pad row. Then issue
// 11 cp.async.bulk stores (~9008B each); <=6 scalar fixups per row.
// ---------------------------------------------------------------------------
__global__ void __launch_bounds__(256) upsample_kernel(float* __restrict__ out) {
    __shared__ __align__(16) float sbuf[5][2264];   // 2264*4 = 9056, 16 | 9056

    const int blk = blockIdx.x;                     // 0 .. 614
    const int c = blk / HO;
    const int oh = blk - c * HO;
    const int tid = threadIdx.x;

    const float* __restrict__ midc = g_mid + c * (HO * HO) + oh * HO;

    // Zero buffer (pad-row source)
    for (int x = tid; x < 2264; x += 256) sbuf[4][x] = 0.0f;

    // Template T[x] = (x%11 < 10) ? mid[x/11] : 0, plus shifts 1..3
    for (int x = tid; x < OUT; x += 256) {
        const unsigned o = (unsigned)x / 11u;
        const unsigned j = (unsigned)x - o * 11u;
        const float v = (j < 10u) ? __ldg(midc + o) : 0.0f;
        sbuf[0][x] = v;
        if (x >= 1) sbuf[1][x - 1] = v;
        if (x >= 2) sbuf[2][x - 2] = v;
        if (x >= 3) sbuf[3][x - 3] = v;
    }
    __syncthreads();
    asm volatile("fence.proxy.async.shared::cta;" ::: "memory");

    const size_t base0 = ((size_t)c * OUT + (size_t)oh * 11) * (size_t)OUT;

    // Scalar head/tail fixups: 11 rows x (<=3 head + <=3 tail)
    if (tid < 88) {
        const float m0 = __ldg(midc);
        const float mL = __ldg(midc + 204);
        const int r = tid >> 3;                     // 0..10
        const int k = tid & 7;
        const size_t gb = base0 + (size_t)r * OUT;
        const int hr = (int)((4u - ((unsigned)gb & 3u)) & 3u);
        const int nf = (((OUT - hr) * 4) & ~15) >> 2;
        const bool live = (r < 10);
        if (k < 4) {
            if (k < hr) out[gb + k] = live ? m0 : 0.0f;     // x<=2: ow=0,j<10
        } else {
            const int x = hr + nf + (k - 4);                // x >= 2252
            if (x < OUT) out[gb + x] = (live && x < 2254) ? mL : 0.0f;
        }
    }

    // TMA bulk stores: one per row, aligned body
    if (tid == 0) {
#pragma unroll
        for (int r = 0; r < 11; r++) {
            const size_t gb = base0 + (size_t)r * OUT;
            const int hr = (int)((4u - ((unsigned)gb & 3u)) & 3u);
            const int nbytes = ((OUT - hr) * 4) & ~15;      // 9008 or 9020->9008
            const int bufi = (r < 10) ? hr : 4;
            float* gdst = out + gb + (size_t)hr;
            const unsigned saddr = smem_u32(&sbuf[bufi][0]);
            asm volatile(
                "cp.async.bulk.global.shared::cta.bulk_group [%0], [%1], %2;"
                :: "l"(gdst), "r"(saddr), "r"(nbytes) : "memory");
        }
        asm volatile("cp.async.bulk.commit_group;" ::: "memory");
        asm volatile("cp.async.bulk.wait_group 0;" ::: "memory");
    }
}

extern "C" void kernel_launch(void* const* d_in, const int* in_sizes, int n_in,
                              void* d_out, int out_size) {
    const float* rgb = (const float*)d_in[0];
    float* out = (float*)d_out;

    const int blocks1 = (CELLS + 7) / 8;       // one warp per cell, 8/block
    cell_kernel<<<blocks1, 256>>>(rgb);

    upsample_kernel<<<BANDS, 256>>>(out);      // one block per 11-row band
}